// round 6
// baseline (speedup 1.0000x reference)
#include <cuda_runtime.h>
#include <cuda_bf16.h>
#include <cstdint>

// Correlation layer (FlowNet-style), MAX_DISP=4.
// first, second: (B=4, C=256, H=128, W=224) fp32 NCHW
// out: (B, 81, H, W) fp32
//
// R5: 256-thread blocks (2 resident/SM) + fma.rn.f32x2 packed inner loop.

#define B_   4
#define C_   256
#define H_   128
#define W_   224
#define P_   4
#define D_   9      // 2P+1
#define ND_  81

#define TX    56    // x-tile width (224 = 4*56)
#define YT    2     // y rows per block
#define XPT   4     // x pixels per thread
#define XT    14    // x-thread count (56/4)
#define CC    8     // channels per smem chunk
#define NCHUNK (C_ / CC)   // 32

#define SWID  64    // second tile width incl. halo (56+8)
#define SROW  68    // padded smem row stride (floats)
#define SH    10    // second rows incl. halo (2+8)
#define FROW  56    // first smem row stride (floats)

#define SCH   (SH * SROW)        // 680 floats per channel (second)
#define FCH   (YT * FROW)        // 112 floats per channel (first)
#define SBUF_FLOATS (CC * SCH)   // 5440
#define FBUF_FLOATS (CC * FCH)   // 896
#define SBUF_BYTES  (SBUF_FLOATS * 4)   // 21760
#define FBUF_BYTES  (FBUF_FLOATS * 4)   // 3584
#define SMEM_TOTAL  (2 * SBUF_BYTES + 2 * FBUF_BYTES)  // 50688

#define S_F4_PER_CH   (SH * (SWID / 4))          // 160 float4 per channel
#define S_F4_TOTAL    (CC * S_F4_PER_CH)         // 1280
#define F_F4_TOTAL    (CC * YT * (FROW / 4))     // 224

#define NTHR   256
#define NWORK  (XT * D_ * YT)    // 252
#define SSLOTS 5                 // 1280 / 256

typedef unsigned long long u64;

__device__ __forceinline__ void cp16(uint32_t dst, const float* src, int sz) {
    asm volatile("cp.async.cg.shared.global [%0], [%1], 16, %2;\n"
                 :: "r"(dst), "l"(src), "r"(sz));
}
__device__ __forceinline__ void cp_commit() {
    asm volatile("cp.async.commit_group;\n");
}
__device__ __forceinline__ void cp_wait1() {
    asm volatile("cp.async.wait_group 1;\n");
}
__device__ __forceinline__ u64 pack2(float lo, float hi) {
    u64 r;
    asm("mov.b64 %0, {%1, %2};" : "=l"(r) : "f"(lo), "f"(hi));
    return r;
}
__device__ __forceinline__ void unpack2(float& lo, float& hi, u64 v) {
    asm("mov.b64 {%0, %1}, %2;" : "=f"(lo), "=f"(hi) : "l"(v));
}
__device__ __forceinline__ u64 fma2(u64 a, u64 b, u64 c) {
    u64 r;
    asm("fma.rn.f32x2 %0, %1, %2, %3;" : "=l"(r) : "l"(a), "l"(b), "l"(c));
    return r;
}

__global__ __launch_bounds__(NTHR, 2)
void corr_kernel(const float* __restrict__ first,
                 const float* __restrict__ second,
                 float* __restrict__ out)
{
    extern __shared__ float dyn[];
    float* sbase = dyn;                       // 2 second buffers
    float* fbase = dyn + 2 * SBUF_FLOATS;     // 2 first buffers

    const int xt = blockIdx.x;          // 0..3
    const int y0 = blockIdx.y * YT;     // 0..126
    const int b  = blockIdx.z;          // 0..3
    const int x0 = xt * TX;

    const int tid = threadIdx.x;        // 0..255
    const bool active = (tid < NWORK);
    const int w_  = active ? tid : (NWORK - 1);
    const int tx  = w_ % XT;            // 0..13
    const int r1  = w_ / XT;
    const int dy  = r1 % D_;            // 0..8
    const int ly  = r1 / D_;            // 0..1

    const float* img_base = first  + (size_t)b * C_ * H_ * W_;
    const float* sec_base = second + (size_t)b * C_ * H_ * W_;

    // ---- precompute second-tile cp.async slots (5 per thread) ----
    const float* sp[SSLOTS];
    uint32_t     sdst[SSLOTS];
    int          ssz[SSLOTS];
#pragma unroll
    for (int j = 0; j < SSLOTS; j++) {
        int pos = tid + j * NTHR;                 // < 1280 always
        int c   = pos / S_F4_PER_CH;
        int rem = pos - c * S_F4_PER_CH;
        int r   = rem >> 4;           // /16
        int xq  = rem & 15;
        int gy  = y0 - P_ + r;
        int gxs = x0 - P_ + xq * 4;
        bool valid = ((unsigned)gy < (unsigned)H_) && ((unsigned)gxs < (unsigned)(W_ - 3));
        ssz[j] = valid ? 16 : 0;
        sp[j]  = sec_base + ((size_t)c * H_ * W_ + (valid ? (gy * W_ + gxs) : 0));
        sdst[j] = (uint32_t)__cvta_generic_to_shared(
                      &sbase[c * SCH + r * SROW + xq * 4]);
    }
    // ---- precompute first-tile slot (tid < 224) ----
    const bool fact = (tid < F_F4_TOTAL);
    int ft  = fact ? tid : 0;
    int fc  = ft / (YT * (FROW / 4));            // /28
    int frm = ft - fc * (YT * (FROW / 4));
    int fr  = frm / (FROW / 4);                  // /14
    int fxq = frm - fr * (FROW / 4);
    const float* fp = img_base + ((size_t)fc * H_ * W_ + (y0 + fr) * W_ + x0 + fxq * 4);
    uint32_t fdst = (uint32_t)__cvta_generic_to_shared(
                        &fbase[fc * FCH + fr * FROW + fxq * 4]);

    // acc pairs: p=0 -> pixels (0,1), p=1 -> pixels (2,3); d = 0..8
    u64 accp[2][D_];
#pragma unroll
    for (int p = 0; p < 2; p++)
#pragma unroll
        for (int d = 0; d < D_; d++)
            accp[p][d] = 0ull;

    // ---- prefetch chunk 0 into buf 0 ----
    {
#pragma unroll
        for (int j = 0; j < SSLOTS; j++)
            cp16(sdst[j], sp[j], ssz[j]);
        if (fact) cp16(fdst, fp, 16);
        cp_commit();
    }

    const int s_ro = (ly + dy) * SROW + tx * XPT;
    const int f_ro = ly * FROW + tx * XPT;

    for (int k = 0; k < NCHUNK; k++) {
        if (k + 1 < NCHUNK) {
            const size_t coff = (size_t)(k + 1) * (CC * H_ * W_);
            const uint32_t db = ((k + 1) & 1) ? SBUF_BYTES : 0;
            const uint32_t fb = ((k + 1) & 1) ? FBUF_BYTES : 0;
#pragma unroll
            for (int j = 0; j < SSLOTS; j++)
                cp16(sdst[j] + db, sp[j] + coff, ssz[j]);
            if (fact) cp16(fdst + fb, fp + coff, 16);
        }
        cp_commit();
        cp_wait1();           // chunk k resident
        __syncthreads();

        const float* sb  = sbase + (k & 1) * SBUF_FLOATS + s_ro;
        const float* fbp = fbase + (k & 1) * FBUF_FLOATS + f_ro;

#pragma unroll
        for (int c = 0; c < CC; c++) {
            const float4 f4 = *(const float4*)(fbp + c * FCH);
            const float* srow = sb + c * SCH;
            float w[12];
            *(float4*)&w[0] = *(const float4*)&srow[0];
            *(float4*)&w[4] = *(const float4*)&srow[4];
            *(float4*)&w[8] = *(const float4*)&srow[8];

            const u64 fp0 = pack2(f4.x, f4.y);
            const u64 fp1 = pack2(f4.z, f4.w);
            u64 wp[11];
#pragma unroll
            for (int j = 0; j < 11; j++)
                wp[j] = pack2(w[j], w[j + 1]);

#pragma unroll
            for (int d = 0; d < D_; d++) {
                accp[0][d] = fma2(fp0, wp[d],     accp[0][d]);
                accp[1][d] = fma2(fp1, wp[d + 2], accp[1][d]);
            }
        }
        __syncthreads();      // protect buffer (k&1) before refill at k+2
    }

    // ---- store: 9 float4 per worker ----
    if (active) {
        const float scale = 1.0f / (float)C_;
        const int y  = y0 + ly;
        const int xo = x0 + tx * XPT;
#pragma unroll
        for (int d = 0; d < D_; d++) {
            const int ch = dy * D_ + d;
            float4 o;
            unpack2(o.x, o.y, accp[0][d]);
            unpack2(o.z, o.w, accp[1][d]);
            o.x *= scale; o.y *= scale; o.z *= scale; o.w *= scale;
            *(float4*)&out[(((size_t)b * ND_ + ch) * H_ + y) * W_ + xo] = o;
        }
    }
}

extern "C" void kernel_launch(void* const* d_in, const int* in_sizes, int n_in,
                              void* d_out, int out_size)
{
    const float* first  = (const float*)d_in[0];
    const float* second = (const float*)d_in[1];
    float* out = (float*)d_out;

    cudaFuncSetAttribute(corr_kernel,
                         cudaFuncAttributeMaxDynamicSharedMemorySize, SMEM_TOTAL);

    dim3 grid(W_ / TX, H_ / YT, B_);   // (4, 64, 4) = 1024 blocks
    dim3 block(NTHR);                  // 256
    corr_kernel<<<grid, block, SMEM_TOTAL>>>(first, second, out);
}

// round 7
// speedup vs baseline: 1.2964x; 1.2964x over previous
#include <cuda_runtime.h>
#include <cuda_bf16.h>
#include <cstdint>

// Correlation layer (FlowNet-style), MAX_DISP=4.
// first, second: (B=4, C=256, H=128, W=224) fp32 NCHW
// out: (B, 81, H, W) fp32
//
// R7: R4 compute shape (YT=4, scalar FFMA, CC=8, cp.async double buffer)
//     + TX=28 / 256-thread blocks so 2 blocks co-reside per SM
//     + conflict-free smem stride (60 floats == 28 mod 32).

#define B_   4
#define C_   256
#define H_   128
#define W_   224
#define P_   4
#define D_   9      // 2P+1
#define ND_  81

#define TX    28    // x-tile width (224 = 8*28)
#define YT    4     // y rows per block
#define XPT   4     // x pixels per thread
#define XT    7     // x-thread count (28/4)
#define CC    8     // channels per smem chunk
#define NCHUNK (C_ / CC)   // 32

#define SWID  36    // second tile width incl. halo (28+8) -> 9 float4
#define SROW  60    // padded smem row stride (floats); 60 % 32 == 28 -> conflict-free
#define SH    12    // second rows incl. halo (4+8)
#define FROW  28    // first smem row stride (floats)

#define SCH   (SH * SROW)        // 720 floats per channel (second)
#define FCH   (YT * FROW)        // 112 floats per channel (first)
#define SBUF_FLOATS (CC * SCH)   // 5760
#define FBUF_FLOATS (CC * FCH)   // 896
#define SBUF_BYTES  (SBUF_FLOATS * 4)   // 23040
#define FBUF_BYTES  (FBUF_FLOATS * 4)   // 3584
#define SMEM_TOTAL  (2 * SBUF_BYTES + 2 * FBUF_BYTES)  // 53248

#define S_F4_PER_CH   (SH * (SWID / 4))          // 108 float4 per channel
#define S_F4_TOTAL    (CC * S_F4_PER_CH)         // 864
#define F_F4_TOTAL    (CC * YT * (FROW / 4))     // 224

#define NTHR   256
#define NWORK  (XT * D_ * YT)    // 252
#define SSLOTS 4                 // ceil(864 / 256)

__device__ __forceinline__ void cp16(uint32_t dst, const float* src, int sz) {
    asm volatile("cp.async.cg.shared.global [%0], [%1], 16, %2;\n"
                 :: "r"(dst), "l"(src), "r"(sz));
}
__device__ __forceinline__ void cp_commit() {
    asm volatile("cp.async.commit_group;\n");
}
__device__ __forceinline__ void cp_wait1() {
    asm volatile("cp.async.wait_group 1;\n");
}

__global__ __launch_bounds__(NTHR, 2)
void corr_kernel(const float* __restrict__ first,
                 const float* __restrict__ second,
                 float* __restrict__ out)
{
    extern __shared__ float dyn[];
    float* sbase = dyn;                       // 2 second buffers
    float* fbase = dyn + 2 * SBUF_FLOATS;     // 2 first buffers

    const int xt = blockIdx.x;          // 0..7
    const int y0 = blockIdx.y * YT;     // 0..124
    const int b  = blockIdx.z;          // 0..3
    const int x0 = xt * TX;

    const int tid = threadIdx.x;        // 0..255
    const bool active = (tid < NWORK);
    const int w_  = active ? tid : (NWORK - 1);
    const int tx  = w_ % XT;            // 0..6
    const int r1  = w_ / XT;
    const int dy  = r1 % D_;            // 0..8
    const int ly  = r1 / D_;            // 0..3

    const float* img_base = first  + (size_t)b * C_ * H_ * W_;
    const float* sec_base = second + (size_t)b * C_ * H_ * W_;

    // ---- precompute second-tile cp.async slots (<=4 per thread) ----
    const float* sp[SSLOTS];
    uint32_t     sdst[SSLOTS];
    int          ssz[SSLOTS];
    bool         sact[SSLOTS];
#pragma unroll
    for (int j = 0; j < SSLOTS; j++) {
        int pos = tid + j * NTHR;
        sact[j] = (pos < S_F4_TOTAL);
        int p   = sact[j] ? pos : 0;
        int c   = p / S_F4_PER_CH;
        int rem = p - c * S_F4_PER_CH;
        int r   = rem / (SWID / 4);
        int xq  = rem - r * (SWID / 4);      // 0..8
        int gy  = y0 - P_ + r;
        int gxs = x0 - P_ + xq * 4;          // 16B aligned; fully in or out
        bool valid = ((unsigned)gy < (unsigned)H_) && ((unsigned)gxs < (unsigned)(W_ - 3));
        ssz[j] = valid ? 16 : 0;
        sp[j]  = sec_base + ((size_t)c * H_ * W_ + (valid ? (gy * W_ + gxs) : 0));
        sdst[j] = (uint32_t)__cvta_generic_to_shared(
                      &sbase[c * SCH + r * SROW + xq * 4]);
    }
    // ---- precompute first-tile slot (tid < 224) ----
    const bool fact = (tid < F_F4_TOTAL);
    int ft  = fact ? tid : 0;
    int fc  = ft / (YT * (FROW / 4));            // /28
    int frm = ft - fc * (YT * (FROW / 4));
    int fr  = frm / (FROW / 4);                  // /7
    int fxq = frm - fr * (FROW / 4);
    const float* fp = img_base + ((size_t)fc * H_ * W_ + (y0 + fr) * W_ + x0 + fxq * 4);
    uint32_t fdst = (uint32_t)__cvta_generic_to_shared(
                        &fbase[fc * FCH + fr * FROW + fxq * 4]);

    float acc[XPT][D_];
#pragma unroll
    for (int i = 0; i < XPT; i++)
#pragma unroll
        for (int d = 0; d < D_; d++)
            acc[i][d] = 0.0f;

    // ---- prefetch chunk 0 into buf 0 ----
    {
#pragma unroll
        for (int j = 0; j < SSLOTS; j++)
            if (sact[j]) cp16(sdst[j], sp[j], ssz[j]);
        if (fact) cp16(fdst, fp, 16);
        cp_commit();
    }

    const int s_ro = (ly + dy) * SROW + tx * XPT;
    const int f_ro = ly * FROW + tx * XPT;

    for (int k = 0; k < NCHUNK; k++) {
        // prefetch k+1 into the other buffer
        if (k + 1 < NCHUNK) {
            const size_t coff = (size_t)(k + 1) * (CC * H_ * W_);
            const uint32_t db = ((k + 1) & 1) ? SBUF_BYTES : 0;
            const uint32_t fb = ((k + 1) & 1) ? FBUF_BYTES : 0;
#pragma unroll
            for (int j = 0; j < SSLOTS; j++)
                if (sact[j]) cp16(sdst[j] + db, sp[j] + coff, ssz[j]);
            if (fact) cp16(fdst + fb, fp + coff, 16);
        }
        cp_commit();
        cp_wait1();           // chunk k resident
        __syncthreads();

        const float* sb  = sbase + (k & 1) * SBUF_FLOATS + s_ro;
        const float* fbp = fbase + (k & 1) * FBUF_FLOATS + f_ro;

#pragma unroll
        for (int c = 0; c < CC; c++) {
            const float4 f4 = *(const float4*)(fbp + c * FCH);
            const float* srow = sb + c * SCH;
            float w[12];
            *(float4*)&w[0] = *(const float4*)&srow[0];
            *(float4*)&w[4] = *(const float4*)&srow[4];
            *(float4*)&w[8] = *(const float4*)&srow[8];
            const float f0 = f4.x, f1 = f4.y, f2 = f4.z, f3 = f4.w;
#pragma unroll
            for (int d = 0; d < D_; d++) {
                acc[0][d] += f0 * w[0 + d];
                acc[1][d] += f1 * w[1 + d];
                acc[2][d] += f2 * w[2 + d];
                acc[3][d] += f3 * w[3 + d];
            }
        }
        __syncthreads();      // protect buffer (k&1) before refill at k+2
    }

    // ---- store: 9 float4 per worker ----
    if (active) {
        const float scale = 1.0f / (float)C_;
        const int y  = y0 + ly;
        const int xo = x0 + tx * XPT;
#pragma unroll
        for (int d = 0; d < D_; d++) {
            const int ch = dy * D_ + d;
            float4 o;
            o.x = acc[0][d] * scale;
            o.y = acc[1][d] * scale;
            o.z = acc[2][d] * scale;
            o.w = acc[3][d] * scale;
            *(float4*)&out[(((size_t)b * ND_ + ch) * H_ + y) * W_ + xo] = o;
        }
    }
}

extern "C" void kernel_launch(void* const* d_in, const int* in_sizes, int n_in,
                              void* d_out, int out_size)
{
    const float* first  = (const float*)d_in[0];
    const float* second = (const float*)d_in[1];
    float* out = (float*)d_out;

    cudaFuncSetAttribute(corr_kernel,
                         cudaFuncAttributeMaxDynamicSharedMemorySize, SMEM_TOTAL);

    dim3 grid(W_ / TX, H_ / YT, B_);   // (8, 32, 4) = 1024 blocks
    dim3 block(NTHR);                  // 256
    corr_kernel<<<grid, block, SMEM_TOTAL>>>(first, second, out);
}

// round 10
// speedup vs baseline: 1.8284x; 1.4103x over previous
#include <cuda_runtime.h>
#include <cuda_bf16.h>
#include <cstdint>

// Correlation layer (FlowNet-style), MAX_DISP=4.
// first, second: (B=4, C=256, H=128, W=224) fp32 NCHW
// out: (B, 81, H, W) fp32
//
// R8: TX=56 (cheap x-halo) + YT=2 (256-thr block, 2 resident blocks/SM)
//     + scalar FFMA + cp.async double buffer
//     + SROW=88 (==24 mod 32): fully conflict-free LDS.128 phases.

#define B_   4
#define C_   256
#define H_   128
#define W_   224
#define P_   4
#define D_   9      // 2P+1
#define ND_  81

#define TX    56    // x-tile width (224 = 4*56)
#define YT    2     // y rows per block
#define XPT   4     // x pixels per thread
#define XT    14    // x-thread count (56/4)
#define CC    8     // channels per smem chunk
#define NCHUNK (C_ / CC)   // 32

#define SWID  64    // second tile width incl. halo (56+8)
#define SROW  88    // smem row stride (floats); 88 % 32 == 24 -> conflict-free
#define SH    10    // second rows incl. halo (2+8)
#define FROW  56    // first smem row stride (floats); 56 % 32 == 24 -> conflict-free

#define SCH   (SH * SROW)        // 880 floats per channel (second)
#define FCH   (YT * FROW)        // 112 floats per channel (first)
#define SBUF_FLOATS (CC * SCH)   // 7040
#define FBUF_FLOATS (CC * FCH)   // 896
#define SBUF_BYTES  (SBUF_FLOATS * 4)   // 28160
#define FBUF_BYTES  (FBUF_FLOATS * 4)   // 3584
#define SMEM_TOTAL  (2 * SBUF_BYTES + 2 * FBUF_BYTES)  // 63488

#define S_F4_PER_CH   (SH * (SWID / 4))          // 160 float4 per channel
#define S_F4_TOTAL    (CC * S_F4_PER_CH)         // 1280 = 5 * 256 exactly
#define F_F4_TOTAL    (CC * YT * (FROW / 4))     // 224

#define NTHR   256
#define NWORK  (XT * D_ * YT)    // 252
#define SSLOTS 5                 // 1280 / 256, no remainder

__device__ __forceinline__ void cp16(uint32_t dst, const float* src, int sz) {
    asm volatile("cp.async.cg.shared.global [%0], [%1], 16, %2;\n"
                 :: "r"(dst), "l"(src), "r"(sz));
}
__device__ __forceinline__ void cp_commit() {
    asm volatile("cp.async.commit_group;\n");
}
__device__ __forceinline__ void cp_wait1() {
    asm volatile("cp.async.wait_group 1;\n");
}

__global__ __launch_bounds__(NTHR, 2)
void corr_kernel(const float* __restrict__ first,
                 const float* __restrict__ second,
                 float* __restrict__ out)
{
    extern __shared__ float dyn[];
    float* sbase = dyn;                       // 2 second buffers
    float* fbase = dyn + 2 * SBUF_FLOATS;     // 2 first buffers

    const int xt = blockIdx.x;          // 0..3
    const int y0 = blockIdx.y * YT;     // 0..126
    const int b  = blockIdx.z;          // 0..3
    const int x0 = xt * TX;

    const int tid = threadIdx.x;        // 0..255
    const bool active = (tid < NWORK);
    const int w_  = active ? tid : (NWORK - 1);
    const int tx  = w_ % XT;            // 0..13
    const int r1  = w_ / XT;            // 0..17
    const int dy  = r1 % D_;            // 0..8
    const int ly  = r1 / D_;            // 0..1

    const float* img_base = first  + (size_t)b * C_ * H_ * W_;
    const float* sec_base = second + (size_t)b * C_ * H_ * W_;

    // ---- precompute second-tile cp.async slots (exactly 5 per thread) ----
    const float* sp[SSLOTS];
    uint32_t     sdst[SSLOTS];
    int          ssz[SSLOTS];
#pragma unroll
    for (int j = 0; j < SSLOTS; j++) {
        int pos = tid + j * NTHR;            // 0..1279
        int c   = pos / S_F4_PER_CH;
        int rem = pos - c * S_F4_PER_CH;
        int r   = rem >> 4;                  // /16 rows
        int xq  = rem & 15;                  // 0..15
        int gy  = y0 - P_ + r;
        int gxs = x0 - P_ + xq * 4;          // 16B aligned; fully in or out
        bool valid = ((unsigned)gy < (unsigned)H_) && ((unsigned)gxs < (unsigned)(W_ - 3));
        ssz[j] = valid ? 16 : 0;
        sp[j]  = sec_base + ((size_t)c * H_ * W_ + (valid ? (gy * W_ + gxs) : 0));
        sdst[j] = (uint32_t)__cvta_generic_to_shared(
                      &sbase[c * SCH + r * SROW + xq * 4]);
    }
    // ---- precompute first-tile slot (tid < 224) ----
    const bool fact = (tid < F_F4_TOTAL);
    int ft  = fact ? tid : 0;
    int fc  = ft / (YT * (FROW / 4));            // /28
    int frm = ft - fc * (YT * (FROW / 4));
    int fr  = frm / (FROW / 4);                  // /14
    int fxq = frm - fr * (FROW / 4);
    const float* fp = img_base + ((size_t)fc * H_ * W_ + (y0 + fr) * W_ + x0 + fxq * 4);
    uint32_t fdst = (uint32_t)__cvta_generic_to_shared(
                        &fbase[fc * FCH + fr * FROW + fxq * 4]);

    float acc[XPT][D_];
#pragma unroll
    for (int i = 0; i < XPT; i++)
#pragma unroll
        for (int d = 0; d < D_; d++)
            acc[i][d] = 0.0f;

    // ---- prefetch chunk 0 into buf 0 ----
    {
#pragma unroll
        for (int j = 0; j < SSLOTS; j++)
            cp16(sdst[j], sp[j], ssz[j]);
        if (fact) cp16(fdst, fp, 16);
        cp_commit();
    }

    const int s_ro = (ly + dy) * SROW + tx * XPT;
    const int f_ro = ly * FROW + tx * XPT;

    for (int k = 0; k < NCHUNK; k++) {
        // prefetch k+1 into the other buffer
        if (k + 1 < NCHUNK) {
            const size_t coff = (size_t)(k + 1) * (CC * H_ * W_);
            const uint32_t db = ((k + 1) & 1) ? SBUF_BYTES : 0;
            const uint32_t fb = ((k + 1) & 1) ? FBUF_BYTES : 0;
#pragma unroll
            for (int j = 0; j < SSLOTS; j++)
                cp16(sdst[j] + db, sp[j] + coff, ssz[j]);
            if (fact) cp16(fdst + fb, fp + coff, 16);
        }
        cp_commit();
        cp_wait1();           // chunk k resident
        __syncthreads();

        const float* sb  = sbase + (k & 1) * SBUF_FLOATS + s_ro;
        const float* fbp = fbase + (k & 1) * FBUF_FLOATS + f_ro;

#pragma unroll
        for (int c = 0; c < CC; c++) {
            const float4 f4 = *(const float4*)(fbp + c * FCH);
            const float* srow = sb + c * SCH;
            float w[12];
            *(float4*)&w[0] = *(const float4*)&srow[0];
            *(float4*)&w[4] = *(const float4*)&srow[4];
            *(float4*)&w[8] = *(const float4*)&srow[8];
            const float f0 = f4.x, f1 = f4.y, f2 = f4.z, f3 = f4.w;
#pragma unroll
            for (int d = 0; d < D_; d++) {
                acc[0][d] += f0 * w[0 + d];
                acc[1][d] += f1 * w[1 + d];
                acc[2][d] += f2 * w[2 + d];
                acc[3][d] += f3 * w[3 + d];
            }
        }
        __syncthreads();      // protect buffer (k&1) before refill at k+2
    }

    // ---- store: 9 float4 per worker ----
    if (active) {
        const float scale = 1.0f / (float)C_;
        const int y  = y0 + ly;
        const int xo = x0 + tx * XPT;
#pragma unroll
        for (int d = 0; d < D_; d++) {
            const int ch = dy * D_ + d;
            float4 o;
            o.x = acc[0][d] * scale;
            o.y = acc[1][d] * scale;
            o.z = acc[2][d] * scale;
            o.w = acc[3][d] * scale;
            *(float4*)&out[(((size_t)b * ND_ + ch) * H_ + y) * W_ + xo] = o;
        }
    }
}

extern "C" void kernel_launch(void* const* d_in, const int* in_sizes, int n_in,
                              void* d_out, int out_size)
{
    const float* first  = (const float*)d_in[0];
    const float* second = (const float*)d_in[1];
    float* out = (float*)d_out;

    cudaFuncSetAttribute(corr_kernel,
                         cudaFuncAttributeMaxDynamicSharedMemorySize, SMEM_TOTAL);

    dim3 grid(W_ / TX, H_ / YT, B_);   // (4, 64, 4) = 1024 blocks
    dim3 block(NTHR);                  // 256
    corr_kernel<<<grid, block, SMEM_TOTAL>>>(first, second, out);
}

// round 11
// speedup vs baseline: 2.7403x; 1.4988x over previous
#include <cuda_runtime.h>
#include <cuda.h>
#include <cuda_bf16.h>
#include <cstdint>

// Correlation layer (FlowNet-style), MAX_DISP=4.
// first, second: (B=4, C=256, H=128, W=224) fp32 NCHW
// out: (B, 81, H, W) fp32
//
// R11: TMA (cp.async.bulk.tensor.3d) double-buffered chunks of CC=16 channels,
//      TX=32/XT=8/YT=4 -> 288 threads all active, phases are single-dy rows
//      (bank-conflict-free for any SROW), 2 blocks/SM, 1 syncthreads/chunk.

#define B_   4
#define C_   256
#define H_   128
#define W_   224
#define P_   4
#define D_   9      // 2P+1
#define ND_  81

#define TX    32    // x-tile width (224 = 7*32)
#define YT    4     // y rows per block
#define XPT   4     // x pixels per thread
#define XT    8     // x-thread count (32/4)
#define CC    16    // channels per smem chunk
#define NCHUNK (C_ / CC)   // 16

#define SWID  40    // second tile width incl. halo (32+8)
#define SROW  40    // dense row stride (TMA tile layout); phases single-dy -> no conflicts
#define SH    12    // second rows incl. halo (4+8)
#define FROW  32    // first row stride

#define SCH   (SH * SROW)        // 480 floats per channel (second)
#define FCH   (YT * FROW)        // 128 floats per channel (first)
#define SBUF_FLOATS (CC * SCH)   // 7680
#define FBUF_FLOATS (CC * FCH)   // 2048
#define SBUF_BYTES  (SBUF_FLOATS * 4)   // 30720
#define FBUF_BYTES  (FBUF_FLOATS * 4)   // 8192
#define OFF_S0   0
#define OFF_S1   SBUF_BYTES
#define OFF_F0   (2 * SBUF_BYTES)
#define OFF_F1   (2 * SBUF_BYTES + FBUF_BYTES)
#define OFF_MBAR (2 * SBUF_BYTES + 2 * FBUF_BYTES)   // 77824
#define SMEM_TOTAL (OFF_MBAR + 64)

#define CHUNK_TX_BYTES (SBUF_BYTES + FBUF_BYTES)     // 38912

#define NTHR 288    // 8 * 9 * 4, every thread is a worker

// ---------------- device-side PTX helpers ----------------
__device__ __forceinline__ uint32_t smem_u32(const void* p) {
    return (uint32_t)__cvta_generic_to_shared(p);
}
__device__ __forceinline__ void mbar_init(uint32_t a, uint32_t cnt) {
    asm volatile("mbarrier.init.shared.b64 [%0], %1;" :: "r"(a), "r"(cnt) : "memory");
}
__device__ __forceinline__ void mbar_expect_tx(uint32_t a, uint32_t bytes) {
    asm volatile("mbarrier.arrive.expect_tx.shared.b64 _, [%0], %1;"
                 :: "r"(a), "r"(bytes) : "memory");
}
__device__ __forceinline__ void mbar_wait(uint32_t a, uint32_t parity) {
    uint32_t done;
    asm volatile(
        "{\n\t.reg .pred p;\n\t"
        "mbarrier.try_wait.parity.acquire.cta.shared::cta.b64 p, [%1], %2;\n\t"
        "selp.b32 %0, 1, 0, p;\n\t}"
        : "=r"(done) : "r"(a), "r"(parity) : "memory");
    if (!done) {
        asm volatile(
            "{\n\t.reg .pred P1;\n\t"
            "WL_%=:\n\t"
            "mbarrier.try_wait.parity.acquire.cta.shared::cta.b64 P1, [%0], %1, 0x989680;\n\t"
            "@P1 bra.uni WD_%=;\n\t"
            "bra.uni WL_%=;\n\t"
            "WD_%=:\n\t}"
            :: "r"(a), "r"(parity) : "memory");
    }
}
__device__ __forceinline__ void tma3d(uint32_t smem_dst, const CUtensorMap* tmap,
                                      int cx, int cy, int cz, uint32_t mbar) {
    asm volatile(
        "cp.async.bulk.tensor.3d.shared::cta.global.tile.mbarrier::complete_tx::bytes "
        "[%0], [%1, {%2, %3, %4}], [%5];"
        :: "r"(smem_dst), "l"(tmap), "r"(cx), "r"(cy), "r"(cz), "r"(mbar)
        : "memory");
}

// ---------------- kernel ----------------
__global__ __launch_bounds__(NTHR, 2)
void corr_kernel(const __grid_constant__ CUtensorMap tm_first,
                 const __grid_constant__ CUtensorMap tm_second,
                 float* __restrict__ out)
{
    extern __shared__ float dyn[];
    const uint32_t smem_base = smem_u32(dyn);
    const uint32_t mbar0 = smem_base + OFF_MBAR;

    const int xt = blockIdx.x;          // 0..6
    const int y0 = blockIdx.y * YT;     // 0..124
    const int b  = blockIdx.z;          // 0..3
    const int x0 = xt * TX;

    const int tid = threadIdx.x;        // 0..287, all workers
    const int tx  = tid & 7;            // 0..7
    const int dy  = (tid >> 3) % D_;    // 0..8
    const int ly  = tid / (XT * D_);    // 0..3

    if (tid == 0) {
        mbar_init(mbar0, 1);
        mbar_init(mbar0 + 8, 1);
    }
    __syncthreads();

    // prefetch chunk 0 into buffer 0
    if (tid == 0) {
        const int cz = b * C_;
        mbar_expect_tx(mbar0, CHUNK_TX_BYTES);
        tma3d(smem_base + OFF_S0, &tm_second, x0 - P_, y0 - P_, cz, mbar0);
        tma3d(smem_base + OFF_F0, &tm_first,  x0,      y0,      cz, mbar0);
    }

    float acc[XPT][D_];
#pragma unroll
    for (int i = 0; i < XPT; i++)
#pragma unroll
        for (int d = 0; d < D_; d++)
            acc[i][d] = 0.0f;

    const int s_ro = (ly + dy) * SROW + tx * XPT;   // within one channel's second tile
    const int f_ro = ly * FROW + tx * XPT;          // within one channel's first tile

    for (int k = 0; k < NCHUNK; k++) {
        // prefetch chunk k+1 into the other buffer
        if (tid == 0 && (k + 1) < NCHUNK) {
            const uint32_t mb = mbar0 + ((k + 1) & 1) * 8;
            const uint32_t so = ((k + 1) & 1) ? OFF_S1 : OFF_S0;
            const uint32_t fo = ((k + 1) & 1) ? OFF_F1 : OFF_F0;
            const int cz = b * C_ + (k + 1) * CC;
            mbar_expect_tx(mb, CHUNK_TX_BYTES);
            tma3d(smem_base + so, &tm_second, x0 - P_, y0 - P_, cz, mb);
            tma3d(smem_base + fo, &tm_first,  x0,      y0,      cz, mb);
        }

        // wait for chunk k
        mbar_wait(mbar0 + (k & 1) * 8, (k >> 1) & 1);

        const float* sb  = dyn + (k & 1) * SBUF_FLOATS + s_ro;
        const float* fbp = dyn + 2 * SBUF_FLOATS + (k & 1) * FBUF_FLOATS + f_ro;

#pragma unroll
        for (int c = 0; c < CC; c++) {
            const float4 f4 = *(const float4*)(fbp + c * FCH);
            const float* srow = sb + c * SCH;
            float w[12];
            *(float4*)&w[0] = *(const float4*)&srow[0];
            *(float4*)&w[4] = *(const float4*)&srow[4];
            *(float4*)&w[8] = *(const float4*)&srow[8];
            const float f0 = f4.x, f1 = f4.y, f2 = f4.z, f3 = f4.w;
#pragma unroll
            for (int d = 0; d < D_; d++) {
                acc[0][d] += f0 * w[0 + d];
                acc[1][d] += f1 * w[1 + d];
                acc[2][d] += f2 * w[2 + d];
                acc[3][d] += f3 * w[3 + d];
            }
        }
        __syncthreads();   // all readers done with buffer (k&1) before refill at k+2
    }

    // ---- store: 9 float4 per thread ----
    const float scale = 1.0f / (float)C_;
    const int y  = y0 + ly;
    const int xo = x0 + tx * XPT;
#pragma unroll
    for (int d = 0; d < D_; d++) {
        const int ch = dy * D_ + d;
        float4 o;
        o.x = acc[0][d] * scale;
        o.y = acc[1][d] * scale;
        o.z = acc[2][d] * scale;
        o.w = acc[3][d] * scale;
        *(float4*)&out[(((size_t)b * ND_ + ch) * H_ + y) * W_ + xo] = o;
    }
}

// ---------------- host ----------------
typedef CUresult (*EncodeTiledFn)(
    CUtensorMap*, CUtensorMapDataType, cuuint32_t, void*,
    const cuuint64_t*, const cuuint64_t*, const cuuint32_t*, const cuuint32_t*,
    CUtensorMapInterleave, CUtensorMapSwizzle, CUtensorMapL2promotion,
    CUtensorMapFloatOOBfill);

static void build_map(EncodeTiledFn fn, CUtensorMap* m, const void* base,
                      uint32_t b0, uint32_t b1, uint32_t b2)
{
    cuuint64_t dims[3]    = {(cuuint64_t)W_, (cuuint64_t)H_, (cuuint64_t)(B_ * C_)};
    cuuint64_t strides[2] = {(cuuint64_t)W_ * 4, (cuuint64_t)W_ * H_ * 4};
    cuuint32_t box[3]     = {b0, b1, b2};
    cuuint32_t es[3]      = {1, 1, 1};
    fn(m, CU_TENSOR_MAP_DATA_TYPE_FLOAT32, 3, (void*)base,
       dims, strides, box, es,
       CU_TENSOR_MAP_INTERLEAVE_NONE, CU_TENSOR_MAP_SWIZZLE_NONE,
       CU_TENSOR_MAP_L2_PROMOTION_L2_128B, CU_TENSOR_MAP_FLOAT_OOB_FILL_NONE);
}

extern "C" void kernel_launch(void* const* d_in, const int* in_sizes, int n_in,
                              void* d_out, int out_size)
{
    const float* first  = (const float*)d_in[0];
    const float* second = (const float*)d_in[1];
    float* out = (float*)d_out;

    void* fp = nullptr;
    cudaDriverEntryPointQueryResult st;
    cudaGetDriverEntryPoint("cuTensorMapEncodeTiled", &fp, cudaEnableDefault, &st);
    EncodeTiledFn enc = (EncodeTiledFn)fp;

    CUtensorMap tm_first, tm_second;
    build_map(enc, &tm_first,  first,  FROW, YT, CC);   // box (32, 4, 16)
    build_map(enc, &tm_second, second, SWID, SH, CC);   // box (40, 12, 16)

    cudaFuncSetAttribute(corr_kernel,
                         cudaFuncAttributeMaxDynamicSharedMemorySize, SMEM_TOTAL);

    dim3 grid(W_ / TX, H_ / YT, B_);   // (7, 32, 4) = 896 blocks
    dim3 block(NTHR);                  // 288
    corr_kernel<<<grid, block, SMEM_TOTAL>>>(tm_first, tm_second, out);
}